// round 9
// baseline (speedup 1.0000x reference)
#include <cuda_runtime.h>
#include <cuda_bf16.h>
#include <cstdint>

// ---------------------------------------------------------------------------
// Net_22625887715641 on GB300 (sm_103a, compiled as compute_103 base ISA)
//
//   K1 feat_kernel : 11x11(x3) valid convs -> g_feat[2][32][384][384]
//   K2 norm_kernel : channel normalize; v=0 -> d_out (x1),
//                    v=1 in place + int8 copy g_xp8 (implicit GEMM B)
//   K3 packA       : A[(o,w)][(p,q)] = masked/shifted x1 -> int8 g_A
//   K4 gemm_kernel : mma.sync m16n8k32 s8 IMMA GEMM 768x768x139008, split-K x4,
//                    512 threads / 16 warps (4/SMSP), warp tile 32x32,
//                    CTA tile 128x128, kc=128 int8, 4-stage cp.async,
//                    cross-iteration ldmatrix fragment pipeline (R5 skeleton)
//   K5 assemble    : g_acc -> x2 permute + scale (incl. 1/127^2)
// ---------------------------------------------------------------------------

#define X1_ELEMS   (32 * 384 * 384)          // 4718592
#define GEMM_K     139008                    // 362*384 int8 elements
#define K_ITERS    1086                      // GEMM_K / 128
#define SPLITS     4
#define IPS        272                       // ceil(1086/4); last split 270

__device__ float   g_feat[2 * X1_ELEMS];
__device__ __align__(16) signed char g_A[(size_t)768 * GEMM_K];   // ~107MB
__device__ __align__(16) signed char g_xp8[34 * 147456];          // int8 x1_prev
__device__ float   g_acc[768 * 768];
__constant__ float c_ft[16 * 3 * 11 * 11];
__constant__ float c_fn[16 * 11 * 11];

// ===================== PTX helpers ========================================
__device__ __forceinline__ uint32_t smem_u32(const void* p) {
    uint32_t a;
    asm("{ .reg .u64 t; cvta.to.shared.u64 t, %1; cvt.u32.u64 %0, t; }"
        : "=r"(a) : "l"(p));
    return a;
}
#define CP_ASYNC16(dst, src) \
    asm volatile("cp.async.cg.shared.global [%0], [%1], 16;" \
                 :: "r"(dst), "l"(src) : "memory")
#define CP_COMMIT() asm volatile("cp.async.commit_group;" ::: "memory")
#define CP_WAIT1()  asm volatile("cp.async.wait_group 1;" ::: "memory")
#define CP_WAIT2()  asm volatile("cp.async.wait_group 2;" ::: "memory")

#define LDSM4(r0, r1, r2, r3, addr) \
    asm volatile("ldmatrix.sync.aligned.m8n8.x4.shared.b16 {%0,%1,%2,%3}, [%4];" \
                 : "=r"(r0), "=r"(r1), "=r"(r2), "=r"(r3) : "r"(addr))

// s8 IMMA, k=32: byte-layout of fragments identical to f16 m16n8k16.
#define IMMA16832(D, a0, a1, a2, a3, b0, b1) \
    asm volatile("mma.sync.aligned.m16n8k32.row.col.s32.s8.s8.s32 " \
                 "{%0,%1,%2,%3}, {%4,%5,%6,%7}, {%8,%9}, {%0,%1,%2,%3};" \
                 : "+r"((D)[0]), "+r"((D)[1]), "+r"((D)[2]), "+r"((D)[3]) \
                 : "r"(a0), "r"(a1), "r"(a2), "r"(a3), "r"(b0), "r"(b1))

// ===========================================================================
// Kernel 1: features (unchanged, 118us)
// ===========================================================================
__global__ void __launch_bounds__(256) feat_kernel(const float* __restrict__ x0,
                                                   const float* __restrict__ x1in)
{
    __shared__ __align__(16) float s_in[3 * 18 * 76];
    const int v  = blockIdx.z;
    const float* src = v ? x1in : x0;
    const int y0 = blockIdx.y * 8;
    const int xb = blockIdx.x * 64;

    for (int e = threadIdx.x; e < 3 * 18 * 74; e += 256) {
        int t = e / (18 * 74);
        int rem = e % (18 * 74);
        int r = rem / 74;
        int cc = rem % 74;
        s_in[(t * 18 + r) * 76 + cc] = src[(t * 394 + (y0 + r)) * 394 + xb + cc];
    }
    __syncthreads();

    for (int it = 0; it < 8; it++) {
        int task = it * 256 + threadIdx.x;
        int c = task >> 6;
        int rem = task & 63;
        int yy = rem >> 3;
        int xc = rem & 7;

        float acc[8];
#pragma unroll
        for (int k = 0; k < 8; k++) acc[k] = 0.f;

        if (c < 16) {
            const float* fb = c_ft + c * 363;
            for (int t = 0; t < 3; t++) {
                for (int i = 0; i < 11; i++) {
                    const float4* rowp = reinterpret_cast<const float4*>(
                        &s_in[(t * 18 + (yy + i)) * 76 + xc * 8]);
                    float w[20];
#pragma unroll
                    for (int m = 0; m < 5; m++) {
                        float4 f4 = rowp[m];
                        w[4 * m] = f4.x; w[4 * m + 1] = f4.y;
                        w[4 * m + 2] = f4.z; w[4 * m + 3] = f4.w;
                    }
#pragma unroll
                    for (int j = 0; j < 11; j++) {
                        float f = fb[t * 121 + i * 11 + j];
#pragma unroll
                        for (int k = 0; k < 8; k++) acc[k] += f * w[j + k];
                    }
                }
            }
#pragma unroll
            for (int k = 0; k < 8; k++) acc[k] = fmaxf(acc[k], 0.f) * 0.5f;
        } else {
            const float* fb = c_fn + (c - 16) * 121;
            const int t = 2;
            for (int i = 0; i < 11; i++) {
                const float4* rowp = reinterpret_cast<const float4*>(
                    &s_in[(t * 18 + (yy + i)) * 76 + xc * 8]);
                float w[20];
#pragma unroll
                for (int m = 0; m < 5; m++) {
                    float4 f4 = rowp[m];
                    w[4 * m] = f4.x; w[4 * m + 1] = f4.y;
                    w[4 * m + 2] = f4.z; w[4 * m + 3] = f4.w;
                }
#pragma unroll
                for (int j = 0; j < 11; j++) {
                    float f = fb[i * 11 + j];
#pragma unroll
                    for (int k = 0; k < 8; k++) acc[k] += f * w[j + k];
                }
            }
#pragma unroll
            for (int k = 0; k < 8; k++) acc[k] = fmaxf(acc[k], 0.f);
        }

        float* dst = g_feat + ((v * 32 + c) * 384 + (y0 + yy)) * 384 + xb + xc * 8;
#pragma unroll
        for (int k = 0; k < 8; k++) dst[k] = acc[k];
    }
}

// ===========================================================================
// Kernel 2: channel normalization (+ int8 emission of x1_prev)
// ===========================================================================
__global__ void norm_kernel(float* __restrict__ out_x1)
{
    int idx = blockIdx.x * blockDim.x + threadIdx.x;
    if (idx >= 2 * 147456) return;
    int v = idx / 147456;
    int pix = idx % 147456;
    float* base = g_feat + v * X1_ELEMS;

    float s = 0.f;
#pragma unroll
    for (int c = 0; c < 32; c++) s += base[c * 147456 + pix];
    float inv = 1.0f / (s + 2.2204460492503131e-16f);

    if (v == 0) {
#pragma unroll
        for (int c = 0; c < 32; c++)
            out_x1[c * 147456 + pix] = base[c * 147456 + pix] * inv;
    } else {
#pragma unroll
        for (int c = 0; c < 32; c++) {
            float val = base[c * 147456 + pix] * inv;
            base[c * 147456 + pix] = val;
            g_xp8[c * 147456 + pix] = (signed char)__float2int_rn(val * 127.f);
        }
    }
}

// ===========================================================================
// Kernel 3: pack A (shifted/masked x1) to int8; rows 736..767 zero.
// One thread per 16 int8. A[r=(o,w)][p*384+q] = quant(x1[o,11+p,11+q-w]) masked.
// ===========================================================================
__global__ void __launch_bounds__(256) packA_kernel(const float* __restrict__ x1)
{
    const int CH = GEMM_K / 16;  // 8688 chunks per row (16 | 384)
    int idx = blockIdx.x * 256 + threadIdx.x;
    if (idx >= 768 * CH) return;
    int r   = idx / CH;
    int c16 = idx % CH;
    int K0  = c16 * 16;
    int p   = K0 / 384;
    int q   = K0 % 384;

    signed char v[16];
    if (r < 736) {
        int o = r / 23, w = r % 23;
        const float* src = x1 + o * 147456 + (11 + p) * 384 + 11 - w;
#pragma unroll
        for (int k = 0; k < 16; k++) {
            int qq = q + k;
            float f = (qq >= w && qq < 362 + w) ? src[qq] : 0.f;
            v[k] = (signed char)__float2int_rn(f * 127.f);
        }
    } else {
#pragma unroll
        for (int k = 0; k < 16; k++) v[k] = 0;
    }
    int4 pk;
    signed char* b = reinterpret_cast<signed char*>(&pk);
#pragma unroll
    for (int k = 0; k < 16; k++) b[k] = v[k];
    reinterpret_cast<int4*>(g_A)[idx] = pk;
}

// ===========================================================================
// Kernel 4: IMMA s8 GEMM. grid (Nt:6, Mt:6, split:4), 512 threads.
// CTA tile 128x128, warp tile 32x32 (16 warps: 4 wm x 4 wn), kc=128 int8,
// 4-stage cp.async, fragment pipeline carried across k-iterations.
// smem: 4 x (A[128][144] + B[128][144]) int8 rows (128B data + 16B pad).
// ===========================================================================
#define TILE_BYTES 18432            // 128*144
#define STAGE_B    (2 * TILE_BYTES)
#define GEMM_SMEM  (4 * STAGE_B)    // 147456

__global__ void __launch_bounds__(512, 1) gemm_kernel()
{
    extern __shared__ char smem[];
    const uint32_t sb = smem_u32(smem);
    const int tid = threadIdx.x;
    const int lane = tid & 31, wid = tid >> 5;
    const int Nt = blockIdx.x, Mt = blockIdx.y, sp = blockIdx.z;
    const int wm = wid & 3, wn = wid >> 2;   // warp tile: rows wm*32, cols wn*32
    const int g = lane >> 2, t4 = lane & 3;

    uint32_t bufA[4], bufB[4];
#pragma unroll
    for (int i = 0; i < 4; i++) {
        bufA[i] = sb + i * STAGE_B;
        bufB[i] = sb + i * STAGE_B + TILE_BYTES;
    }

    // ---- cp.async mapping: 512 threads, 2x16B per operand per tile ----
    const int lr = tid >> 3;         // 0..63
    const int lc = tid & 7;          // 0..7 (16B column chunks of the 128B row)
    const signed char* gA0 = g_A + (size_t)(Mt * 128 + lr) * GEMM_K + lc * 16;
    const signed char* gB0[2];
#pragma unroll
    for (int j = 0; j < 2; j++) {
        int n = Nt * 128 + lr + 64 * j;
        gB0[j] = g_xp8 + (size_t)(n / 23) * 147456 + (n % 23) * 384 + lc * 16;
    }
    const uint32_t dOff = (uint32_t)(lr * 144 + lc * 16);

    const int k0 = sp * IPS;
    const int k1 = (k0 + IPS < K_ITERS) ? (k0 + IPS) : K_ITERS;

#define LOAD_TILE(kt, b) do {                                                  \
        size_t _ko = (size_t)(kt) * 128;                                       \
        _Pragma("unroll")                                                      \
        for (int _j = 0; _j < 2; _j++) {                                       \
            CP_ASYNC16(bufA[b] + dOff + _j * (64 * 144),                       \
                       gA0 + _ko + (size_t)_j * 64 * GEMM_K);                  \
            CP_ASYNC16(bufB[b] + dOff + _j * (64 * 144), gB0[_j] + _ko);       \
        }                                                                      \
    } while (0)

    LOAD_TILE(k0,     (k0) & 3);     CP_COMMIT();
    LOAD_TILE(k0 + 1, (k0 + 1) & 3); CP_COMMIT();
    LOAD_TILE(k0 + 2, (k0 + 2) & 3); CP_COMMIT();

    int acc[2][4][4];
#pragma unroll
    for (int mt = 0; mt < 2; mt++)
#pragma unroll
        for (int nt = 0; nt < 4; nt++)
#pragma unroll
            for (int e = 0; e < 4; e++) acc[mt][nt][e] = 0;

    // ---- per-lane ldmatrix offsets (bytes; identical to bf16 version) ----
    const int matq = lane >> 3, rin = lane & 7;
    const uint32_t offA = (uint32_t)((((matq & 1) * 8 + rin) * 144) + (matq >> 1) * 16);
    const uint32_t offB = (uint32_t)((((matq >> 1) * 8 + rin) * 144) + (matq & 1) * 16);
    const uint32_t aRow = (uint32_t)(wm * 32) * 144;
    const uint32_t bRow = (uint32_t)(wn * 32) * 144;

    // fragment double buffers (pipeline carried across k-iterations)
    uint32_t Af[2][2][4], Bf[2][2][4];

#define LDS_ALL(fb, bA, bB, ks) do {                                           \
        _Pragma("unroll")                                                      \
        for (int _mt = 0; _mt < 2; _mt++)                                      \
            LDSM4(Af[fb][_mt][0], Af[fb][_mt][1], Af[fb][_mt][2], Af[fb][_mt][3], \
                  (bA) + aRow + _mt * (16 * 144) + (ks) * 32 + offA);          \
        _Pragma("unroll")                                                      \
        for (int _p = 0; _p < 2; _p++)                                         \
            LDSM4(Bf[fb][_p][0], Bf[fb][_p][1], Bf[fb][_p][2], Bf[fb][_p][3],  \
                  (bB) + bRow + _p * (16 * 144) + (ks) * 32 + offB);           \
    } while (0)

#define MMA_ALL(fb) do {                                                       \
        _Pragma("unroll")                                                      \
        for (int _p = 0; _p < 2; _p++) {                                       \
            _Pragma("unroll")                                                  \
            for (int _mt = 0; _mt < 2; _mt++) {                                \
                IMMA16832(acc[_mt][2 * _p],     Af[fb][_mt][0], Af[fb][_mt][1], \
                          Af[fb][_mt][2], Af[fb][_mt][3], Bf[fb][_p][0], Bf[fb][_p][1]); \
                IMMA16832(acc[_mt][2 * _p + 1], Af[fb][_mt][0], Af[fb][_mt][1], \
                          Af[fb][_mt][2], Af[fb][_mt][3], Bf[fb][_p][2], Bf[fb][_p][3]); \
            }                                                                  \
        }                                                                      \
    } while (0)

    // Prologue: tile k0 resident (3 committed, wait<=2), preload ks=0 frags.
    CP_WAIT2();
    __syncthreads();
    LDS_ALL(0, bufA[k0 & 3], bufB[k0 & 3], 0);

    for (int kt = k0; kt < k1; kt++) {
        CP_WAIT1();          // tiles kt and kt+1 resident
        __syncthreads();     // all warps done reading slot (kt+3)&3's old tile
        if (kt + 3 < k1) LOAD_TILE(kt + 3, (kt + 3) & 3);
        CP_COMMIT();         // unconditional (possibly empty group)

        const uint32_t cA = bufA[kt & 3],       cB = bufB[kt & 3];
        const uint32_t nA = bufA[(kt + 1) & 3], nB = bufB[(kt + 1) & 3];

        LDS_ALL(1, cA, cB, 1);  MMA_ALL(0);
        LDS_ALL(0, cA, cB, 2);  MMA_ALL(1);
        LDS_ALL(1, cA, cB, 3);  MMA_ALL(0);
        LDS_ALL(0, nA, nB, 0);  MMA_ALL(1);   // prefetch next tile's ks=0
    }

    // ---- epilogue: dequant + atomicAdd into g_acc (split-K reduction) ----
    const float DQ = 1.0f / 16129.0f;  // 1/127^2
    const int row0 = Mt * 128 + wm * 32;
    const int col0 = Nt * 128 + wn * 32;
#pragma unroll
    for (int mt = 0; mt < 2; mt++) {
        int r_lo = row0 + mt * 16 + g;
        int r_hi = r_lo + 8;
#pragma unroll
        for (int nt = 0; nt < 4; nt++) {
            int c = col0 + nt * 8 + 2 * t4;
            bool c0ok = (c < 736), c1ok = (c + 1 < 736);
            if (r_lo < 736) {
                if (c0ok) atomicAdd(&g_acc[r_lo * 768 + c],     (float)acc[mt][nt][0] * DQ);
                if (c1ok) atomicAdd(&g_acc[r_lo * 768 + c + 1], (float)acc[mt][nt][1] * DQ);
            }
            if (r_hi < 736) {
                if (c0ok) atomicAdd(&g_acc[r_hi * 768 + c],     (float)acc[mt][nt][2] * DQ);
                if (c1ok) atomicAdd(&g_acc[r_hi * 768 + c + 1], (float)acc[mt][nt][3] * DQ);
            }
        }
    }
#undef LOAD_TILE
#undef LDS_ALL
#undef MMA_ALL
}

// ===========================================================================
// Kernel 5: assemble x2 from g_acc with permutation + scale
// ===========================================================================
__global__ void assemble_kernel(float* __restrict__ out_x2)
{
    int i = blockIdx.x * 256 + threadIdx.x;
    if (i >= 32 * 32 * 23 * 23) return;
    int w = i % 23;
    int t = i / 23;
    int h = t % 23; t /= 23;
    int d = t % 32;
    int o = t / 32;
    out_x2[i] = g_acc[(o * 23 + w) * 768 + (d * 23 + h)] * (1.0f / 131044.0f);
}

// ===========================================================================
// Launch
// ===========================================================================
extern "C" void kernel_launch(void* const* d_in, const int* in_sizes, int n_in,
                              void* d_out, int out_size)
{
    const float* x  = (const float*)d_in[0];
    const float* xp = (const float*)d_in[1];
    float* out = (float*)d_out;

    void *aft = nullptr, *afn = nullptr, *aacc = nullptr;
    cudaGetSymbolAddress(&aft, c_ft);
    cudaGetSymbolAddress(&afn, c_fn);
    cudaGetSymbolAddress(&aacc, g_acc);
    cudaMemcpyAsync(aft, d_in[2], 5808 * sizeof(float), cudaMemcpyDeviceToDevice, 0);
    cudaMemcpyAsync(afn, d_in[3], 1936 * sizeof(float), cudaMemcpyDeviceToDevice, 0);
    cudaMemsetAsync(aacc, 0, 768 * 768 * sizeof(float), 0);

    dim3 g1(6, 48, 2);
    feat_kernel<<<g1, 256>>>(x, xp);

    norm_kernel<<<(2 * 147456 + 255) / 256, 256>>>(out);

    packA_kernel<<<(768 * (GEMM_K / 16) + 255) / 256, 256>>>(out);

    static bool attr_set = false;
    if (!attr_set) {
        cudaFuncSetAttribute(gemm_kernel, cudaFuncAttributeMaxDynamicSharedMemorySize,
                             GEMM_SMEM);
        attr_set = true;
    }
    dim3 g4(6, 6, SPLITS);
    gemm_kernel<<<g4, 512, GEMM_SMEM>>>();

    assemble_kernel<<<(32 * 32 * 23 * 23 + 255) / 256, 256>>>(out + X1_ELEMS);
}

// round 10
// speedup vs baseline: 2.0855x; 2.0855x over previous
#include <cuda_runtime.h>
#include <cuda_bf16.h>
#include <cstdint>

// ---------------------------------------------------------------------------
// Net_22625887715641 on GB300 (sm_103a, compiled as compute_103 base ISA)
//
//   K1 feat_kernel : 11x11(x3) valid convs -> g_feat[2][32][384][384]
//   K2 norm_kernel : channel normalize; v=0 -> d_out (x1),
//                    v=1 in place + bf16 copy g_xp16 (implicit GEMM B)
//   K3 packA       : A[(o,w)][(p,q)] = masked/shifted x1 -> bf16 g_A
//   K4 gemm_kernel : mma.sync m16n8k16 bf16 GEMM 768x768x139008, split-K x8,
//                    CTA 128x128 / 256 thr / warp tile 32x64, 3-stage cp.async,
//                    single-buffered frags, __launch_bounds__(256,2) -> 2 CTA/SM
//   K5 assemble    : g_acc -> x2 permute + scale
// ---------------------------------------------------------------------------

#define X1_ELEMS   (32 * 384 * 384)          // 4718592
#define GEMM_K     139008                    // 362*384
#define K_ITERS64  2172                      // GEMM_K / 64
#define SPLITS     8
#define IPS        272                       // ceil(2172/8); last split 268

__device__ float   g_feat[2 * X1_ELEMS];
__device__ __align__(16) __nv_bfloat16 g_A[768 * GEMM_K];        // ~213MB
__device__ __align__(16) __nv_bfloat16 g_xp16[34 * 147456];
__device__ float   g_acc[768 * 768];
__constant__ float c_ft[16 * 3 * 11 * 11];
__constant__ float c_fn[16 * 11 * 11];

// ===================== PTX helpers ========================================
__device__ __forceinline__ uint32_t smem_u32(const void* p) {
    uint32_t a;
    asm("{ .reg .u64 t; cvta.to.shared.u64 t, %1; cvt.u32.u64 %0, t; }"
        : "=r"(a) : "l"(p));
    return a;
}
#define CP_ASYNC16(dst, src) \
    asm volatile("cp.async.cg.shared.global [%0], [%1], 16;" \
                 :: "r"(dst), "l"(src) : "memory")
#define CP_COMMIT() asm volatile("cp.async.commit_group;" ::: "memory")
#define CP_WAIT1()  asm volatile("cp.async.wait_group 1;" ::: "memory")

#define LDSM4(r0, r1, r2, r3, addr) \
    asm volatile("ldmatrix.sync.aligned.m8n8.x4.shared.b16 {%0,%1,%2,%3}, [%4];" \
                 : "=r"(r0), "=r"(r1), "=r"(r2), "=r"(r3) : "r"(addr))

#define MMA16816(D, a0, a1, a2, a3, b0, b1) \
    asm volatile("mma.sync.aligned.m16n8k16.row.col.f32.bf16.bf16.f32 " \
                 "{%0,%1,%2,%3}, {%4,%5,%6,%7}, {%8,%9}, {%0,%1,%2,%3};" \
                 : "+f"((D)[0]), "+f"((D)[1]), "+f"((D)[2]), "+f"((D)[3]) \
                 : "r"(a0), "r"(a1), "r"(a2), "r"(a3), "r"(b0), "r"(b1))

// ===========================================================================
// Kernel 1: features (unchanged, 118us)
// ===========================================================================
__global__ void __launch_bounds__(256) feat_kernel(const float* __restrict__ x0,
                                                   const float* __restrict__ x1in)
{
    __shared__ __align__(16) float s_in[3 * 18 * 76];
    const int v  = blockIdx.z;
    const float* src = v ? x1in : x0;
    const int y0 = blockIdx.y * 8;
    const int xb = blockIdx.x * 64;

    for (int e = threadIdx.x; e < 3 * 18 * 74; e += 256) {
        int t = e / (18 * 74);
        int rem = e % (18 * 74);
        int r = rem / 74;
        int cc = rem % 74;
        s_in[(t * 18 + r) * 76 + cc] = src[(t * 394 + (y0 + r)) * 394 + xb + cc];
    }
    __syncthreads();

    for (int it = 0; it < 8; it++) {
        int task = it * 256 + threadIdx.x;
        int c = task >> 6;
        int rem = task & 63;
        int yy = rem >> 3;
        int xc = rem & 7;

        float acc[8];
#pragma unroll
        for (int k = 0; k < 8; k++) acc[k] = 0.f;

        if (c < 16) {
            const float* fb = c_ft + c * 363;
            for (int t = 0; t < 3; t++) {
                for (int i = 0; i < 11; i++) {
                    const float4* rowp = reinterpret_cast<const float4*>(
                        &s_in[(t * 18 + (yy + i)) * 76 + xc * 8]);
                    float w[20];
#pragma unroll
                    for (int m = 0; m < 5; m++) {
                        float4 f4 = rowp[m];
                        w[4 * m] = f4.x; w[4 * m + 1] = f4.y;
                        w[4 * m + 2] = f4.z; w[4 * m + 3] = f4.w;
                    }
#pragma unroll
                    for (int j = 0; j < 11; j++) {
                        float f = fb[t * 121 + i * 11 + j];
#pragma unroll
                        for (int k = 0; k < 8; k++) acc[k] += f * w[j + k];
                    }
                }
            }
#pragma unroll
            for (int k = 0; k < 8; k++) acc[k] = fmaxf(acc[k], 0.f) * 0.5f;
        } else {
            const float* fb = c_fn + (c - 16) * 121;
            const int t = 2;
            for (int i = 0; i < 11; i++) {
                const float4* rowp = reinterpret_cast<const float4*>(
                    &s_in[(t * 18 + (yy + i)) * 76 + xc * 8]);
                float w[20];
#pragma unroll
                for (int m = 0; m < 5; m++) {
                    float4 f4 = rowp[m];
                    w[4 * m] = f4.x; w[4 * m + 1] = f4.y;
                    w[4 * m + 2] = f4.z; w[4 * m + 3] = f4.w;
                }
#pragma unroll
                for (int j = 0; j < 11; j++) {
                    float f = fb[i * 11 + j];
#pragma unroll
                    for (int k = 0; k < 8; k++) acc[k] += f * w[j + k];
                }
            }
#pragma unroll
            for (int k = 0; k < 8; k++) acc[k] = fmaxf(acc[k], 0.f);
        }

        float* dst = g_feat + ((v * 32 + c) * 384 + (y0 + yy)) * 384 + xb + xc * 8;
#pragma unroll
        for (int k = 0; k < 8; k++) dst[k] = acc[k];
    }
}

// ===========================================================================
// Kernel 2: channel normalization (+ bf16 emission of x1_prev)
// ===========================================================================
__global__ void norm_kernel(float* __restrict__ out_x1)
{
    int idx = blockIdx.x * blockDim.x + threadIdx.x;
    if (idx >= 2 * 147456) return;
    int v = idx / 147456;
    int pix = idx % 147456;
    float* base = g_feat + v * X1_ELEMS;

    float s = 0.f;
#pragma unroll
    for (int c = 0; c < 32; c++) s += base[c * 147456 + pix];
    float inv = 1.0f / (s + 2.2204460492503131e-16f);

    if (v == 0) {
#pragma unroll
        for (int c = 0; c < 32; c++)
            out_x1[c * 147456 + pix] = base[c * 147456 + pix] * inv;
    } else {
#pragma unroll
        for (int c = 0; c < 32; c++) {
            float val = base[c * 147456 + pix] * inv;
            base[c * 147456 + pix] = val;
            g_xp16[c * 147456 + pix] = __float2bfloat16(val);
        }
    }
}

// ===========================================================================
// Kernel 3: pack A (shifted/masked x1) to bf16; rows 736..767 zero.
// ===========================================================================
__global__ void __launch_bounds__(256) packA_kernel(const float* __restrict__ x1)
{
    const int CH = GEMM_K / 8;  // 17376
    int idx = blockIdx.x * 256 + threadIdx.x;
    if (idx >= 768 * CH) return;
    int r  = idx / CH;
    int c8 = idx % CH;
    int K0 = c8 * 8;
    int p  = K0 / 384;
    int q  = K0 % 384;

    __nv_bfloat16 v[8];
    if (r < 736) {
        int o = r / 23, w = r % 23;
        const float* src = x1 + o * 147456 + (11 + p) * 384 + 11 - w;
#pragma unroll
        for (int k = 0; k < 8; k++) {
            int qq = q + k;
            float f = (qq >= w && qq < 362 + w) ? src[qq] : 0.f;
            v[k] = __float2bfloat16(f);
        }
    } else {
#pragma unroll
        for (int k = 0; k < 8; k++) v[k] = __float2bfloat16(0.f);
    }
    uint4 pk;
    uint16_t* b = reinterpret_cast<uint16_t*>(&pk);
#pragma unroll
    for (int k = 0; k < 8; k++) b[k] = *reinterpret_cast<uint16_t*>(&v[k]);
    reinterpret_cast<uint4*>(g_A)[idx] = pk;
}

// ===========================================================================
// Kernel 4: mma.sync bf16 GEMM. grid (Nt:6, Mt:6, split:8), 256 threads.
// CTA tile 128x128, warp tile 32x64 (8 warps: 4 wm x 2 wn), kc=64,
// 3-stage cp.async, single-buffered frags, 2 CTAs/SM (regs<=128, smem 110KB).
// smem: 3 x (A[128][72] + B[128][72]) bf16, stride 144 B = 110592 B.
// ===========================================================================
#define TILE_BYTES 18432            // 128*144
#define STAGE_B    (2 * TILE_BYTES)
#define GEMM_SMEM  (3 * STAGE_B)    // 110592

__global__ void __launch_bounds__(256, 2) gemm_kernel()
{
    extern __shared__ char smem[];
    const uint32_t sb = smem_u32(smem);
    const int tid = threadIdx.x;
    const int lane = tid & 31, wid = tid >> 5;
    const int Nt = blockIdx.x, Mt = blockIdx.y, sp = blockIdx.z;
    const int wm = wid & 3, wn = wid >> 2;   // warp tile: rows wm*32, cols wn*64
    const int g = lane >> 2, t4 = lane & 3;

    uint32_t bufA[3], bufB[3];
#pragma unroll
    for (int i = 0; i < 3; i++) {
        bufA[i] = sb + i * STAGE_B;
        bufB[i] = sb + i * STAGE_B + TILE_BYTES;
    }

    // ---- cp.async mapping: 4 chunks (16B) per operand per thread per tile ----
    const int lr = tid >> 3;         // 0..31
    const int lc = tid & 7;          // 0..7
    const __nv_bfloat16* gA0 = g_A + (size_t)(Mt * 128 + lr) * GEMM_K + lc * 8;
    const __nv_bfloat16* gB0[4];
#pragma unroll
    for (int j = 0; j < 4; j++) {
        int n = Nt * 128 + lr + 32 * j;
        gB0[j] = g_xp16 + (size_t)(n / 23) * 147456 + (n % 23) * 384 + lc * 8;
    }
    const uint32_t dOff = (uint32_t)(lr * 144 + lc * 16);

    const int k0 = sp * IPS;
    const int k1 = (k0 + IPS < K_ITERS64) ? (k0 + IPS) : K_ITERS64;

#define LOAD_TILE(kt, b) do {                                                  \
        size_t _ko = (size_t)(kt) * 64;                                        \
        _Pragma("unroll")                                                      \
        for (int _j = 0; _j < 4; _j++) {                                       \
            CP_ASYNC16(bufA[b] + dOff + _j * (32 * 144),                       \
                       gA0 + _ko + (size_t)_j * 32 * GEMM_K);                  \
            CP_ASYNC16(bufB[b] + dOff + _j * (32 * 144), gB0[_j] + _ko);       \
        }                                                                      \
    } while (0)

    int s0 = k0 % 3, s1 = (k0 + 1) % 3;
    LOAD_TILE(k0,     s0); CP_COMMIT();
    LOAD_TILE(k0 + 1, s1); CP_COMMIT();

    float acc[2][8][4];
#pragma unroll
    for (int mt = 0; mt < 2; mt++)
#pragma unroll
        for (int nt = 0; nt < 8; nt++)
#pragma unroll
            for (int e = 0; e < 4; e++) acc[mt][nt][e] = 0.f;

    // ---- per-lane ldmatrix offsets (bytes) ----
    const int matq = lane >> 3, rin = lane & 7;
    const uint32_t offA = (uint32_t)((((matq & 1) * 8 + rin) * 144) + (matq >> 1) * 16);
    const uint32_t offB = (uint32_t)((((matq >> 1) * 8 + rin) * 144) + (matq & 1) * 16);
    const uint32_t aRow = (uint32_t)(wm * 32) * 144;
    const uint32_t bRow = (uint32_t)(wn * 64) * 144;

    // single-buffered fragments (cross-CTA overlap hides LDSM latency)
    uint32_t Af[2][4], Bf[4][4];

    int slot = s0;
    for (int kt = k0; kt < k1; kt++) {
        CP_WAIT1();          // tile kt resident (kt+1 may still be in flight)
        __syncthreads();     // all warps done reading this slot's previous tile
        if (kt + 2 < k1) {
            int ns = (slot + 2) % 3;
            LOAD_TILE(kt + 2, ns);
        }
        CP_COMMIT();         // unconditional (possibly empty group)

        const uint32_t cA = bufA[slot], cB = bufB[slot];

#pragma unroll
        for (int ks = 0; ks < 4; ks++) {
#pragma unroll
            for (int mt = 0; mt < 2; mt++)
                LDSM4(Af[mt][0], Af[mt][1], Af[mt][2], Af[mt][3],
                      cA + aRow + mt * (16 * 144) + ks * 32 + offA);
#pragma unroll
            for (int p = 0; p < 4; p++)
                LDSM4(Bf[p][0], Bf[p][1], Bf[p][2], Bf[p][3],
                      cB + bRow + p * (16 * 144) + ks * 32 + offB);
#pragma unroll
            for (int p = 0; p < 4; p++) {
#pragma unroll
                for (int mt = 0; mt < 2; mt++) {
                    MMA16816(acc[mt][2 * p],     Af[mt][0], Af[mt][1],
                             Af[mt][2], Af[mt][3], Bf[p][0], Bf[p][1]);
                    MMA16816(acc[mt][2 * p + 1], Af[mt][0], Af[mt][1],
                             Af[mt][2], Af[mt][3], Bf[p][2], Bf[p][3]);
                }
            }
        }
        slot = (slot + 1) % 3;
    }

    // ---- epilogue: atomicAdd into g_acc (split-K reduction) ----
    const int row0 = Mt * 128 + wm * 32;
    const int col0 = Nt * 128 + wn * 64;
#pragma unroll
    for (int mt = 0; mt < 2; mt++) {
        int r_lo = row0 + mt * 16 + g;
        int r_hi = r_lo + 8;
#pragma unroll
        for (int nt = 0; nt < 8; nt++) {
            int c = col0 + nt * 8 + 2 * t4;
            bool c0ok = (c < 736), c1ok = (c + 1 < 736);
            if (r_lo < 736) {
                if (c0ok) atomicAdd(&g_acc[r_lo * 768 + c],     acc[mt][nt][0]);
                if (c1ok) atomicAdd(&g_acc[r_lo * 768 + c + 1], acc[mt][nt][1]);
            }
            if (r_hi < 736) {
                if (c0ok) atomicAdd(&g_acc[r_hi * 768 + c],     acc[mt][nt][2]);
                if (c1ok) atomicAdd(&g_acc[r_hi * 768 + c + 1], acc[mt][nt][3]);
            }
        }
    }
#undef LOAD_TILE
}

// ===========================================================================
// Kernel 5: assemble x2 from g_acc with permutation + scale
// ===========================================================================
__global__ void assemble_kernel(float* __restrict__ out_x2)
{
    int i = blockIdx.x * 256 + threadIdx.x;
    if (i >= 32 * 32 * 23 * 23) return;
    int w = i % 23;
    int t = i / 23;
    int h = t % 23; t /= 23;
    int d = t % 32;
    int o = t / 32;
    out_x2[i] = g_acc[(o * 23 + w) * 768 + (d * 23 + h)] * (1.0f / 131044.0f);
}

// ===========================================================================
// Launch
// ===========================================================================
extern "C" void kernel_launch(void* const* d_in, const int* in_sizes, int n_in,
                              void* d_out, int out_size)
{
    const float* x  = (const float*)d_in[0];
    const float* xp = (const float*)d_in[1];
    float* out = (float*)d_out;

    void *aft = nullptr, *afn = nullptr, *aacc = nullptr;
    cudaGetSymbolAddress(&aft, c_ft);
    cudaGetSymbolAddress(&afn, c_fn);
    cudaGetSymbolAddress(&aacc, g_acc);
    cudaMemcpyAsync(aft, d_in[2], 5808 * sizeof(float), cudaMemcpyDeviceToDevice, 0);
    cudaMemcpyAsync(afn, d_in[3], 1936 * sizeof(float), cudaMemcpyDeviceToDevice, 0);
    cudaMemsetAsync(aacc, 0, 768 * 768 * sizeof(float), 0);

    dim3 g1(6, 48, 2);
    feat_kernel<<<g1, 256>>>(x, xp);

    norm_kernel<<<(2 * 147456 + 255) / 256, 256>>>(out);

    packA_kernel<<<(768 * (GEMM_K / 8) + 255) / 256, 256>>>(out);

    static bool attr_set = false;
    if (!attr_set) {
        cudaFuncSetAttribute(gemm_kernel, cudaFuncAttributeMaxDynamicSharedMemorySize,
                             GEMM_SMEM);
        attr_set = true;
    }
    dim3 g4(6, 6, SPLITS);
    gemm_kernel<<<g4, 256, GEMM_SMEM>>>();

    assemble_kernel<<<(32 * 32 * 23 * 23 + 255) / 256, 256>>>(out + X1_ELEMS);
}